// round 5
// baseline (speedup 1.0000x reference)
#include <cuda_runtime.h>

// Correlation cost volume (FlowNet-style), MAX_DISP=4 (81 displacements).
// first, second: [B=4, C=128, H=128, W=192] fp32.  out: [B, 81, H, W] fp32,
// out[b,(dy+4)*9+(dx+4),y,x] = (1/C) * sum_c first[b,c,y,x]*second[b,c,y+dy,x+dx]
// (zero padding outside the image).

namespace {
constexpr int Bb = 4, Cc = 128, Hh = 128, Ww = 192;
constexpr int PXT = 2;            // pixels per thread along x
constexpr int GX  = 32;           // thread columns
constexpr int TX  = GX * PXT;     // 64-pixel tile width
constexpr int TY  = 8;            // tile height (threadIdx.y)
constexpr int CCH = 8;            // channels per smem stage
constexpr int NST = Cc / CCH;     // 16 stages
constexpr int SROWS = TY + 2;     // dy span per group = 3 -> TY+2 second rows
constexpr int SW  = TX + 8;       // 72 floats per second row (x halo +-4)
constexpr int SV4 = SW / 4;       // 18 float4 per second row
constexpr int FV4 = TX / 4;       // 16 float4 per first row
constexpr int XT  = Ww / TX;      // 3
constexpr int YT  = Hh / TY;      // 16
constexpr int SEC_F = CCH * SROWS * SW;  // 5760 floats
constexpr int FST_F = CCH * TY * TX;     // 4096 floats
// Over-request dynamic smem to pin occupancy at exactly 2 blocks/SM
// (3 blocks -> 576/444 blocks = 65% last-wave utilization; 2 -> 97%).
constexpr unsigned SMEM_BYTES = 88u * 1024u;
constexpr int NBLOCKS = Bb * XT * YT * 3;  // 576
}  // namespace

__global__ __launch_bounds__(256, 2)
void FunctionCorrelation_17282948399394_kernel(
    const float* __restrict__ first,
    const float* __restrict__ second,
    float* __restrict__ out)
{
    extern __shared__ float smem[];
    float* sec = smem;            // [CCH][SROWS][SW] floats
    float* fst = smem + SEC_F;    // [CCH][TY][TX] floats

    const int tx  = threadIdx.x;              // 0..31
    const int ty  = threadIdx.y;              // 0..7
    const int tid = ty * GX + tx;             // 0..255

    // Decode block id: g fastest so the 3 dy-groups of one spatial tile run
    // concurrently and share second/first tile data in L2.
    int t = blockIdx.x;
    const int g  = t % 3;  t /= 3;            // dy group: dy in {3g-4, 3g-3, 3g-2}
    const int xt = t % XT; t /= XT;
    const int yt = t % YT; t /= YT;
    const int b  = t;

    const int x0  = xt * TX;
    const int y0  = yt * TY;
    const int ys0 = y0 + 3 * g - 4;           // first second-row needed

    float acc[3][9][PXT];
#pragma unroll
    for (int j = 0; j < 3; j++)
#pragma unroll
        for (int dxi = 0; dxi < 9; dxi++)
#pragma unroll
            for (int p = 0; p < PXT; p++)
                acc[j][dxi][p] = 0.0f;

#pragma unroll 1
    for (int st = 0; st < NST; st++) {
        const int c0 = st * CCH;
        __syncthreads();  // previous stage's compute must finish reading smem

        // ---- load second tile: CCH x SROWS x 72 floats (float4, full-vector
        // predication: tile x-boundaries are multiples of 4, so vectors are
        // never partially out of bounds) ----
#pragma unroll 1
        for (int i = tid; i < CCH * SROWS * SV4; i += 256) {
            const int ch  = i / (SROWS * SV4);
            const int rem = i - ch * (SROWS * SV4);
            const int r   = rem / SV4;
            const int k   = rem - r * SV4;
            const int gy  = ys0 + r;
            const int gx  = x0 - 4 + k * 4;
            float4 v = make_float4(0.f, 0.f, 0.f, 0.f);
            if ((unsigned)gy < (unsigned)Hh && (unsigned)gx < (unsigned)Ww)
                v = *reinterpret_cast<const float4*>(
                        second + (((b * Cc + c0 + ch) * Hh + gy) * Ww + gx));
            reinterpret_cast<float4*>(sec)[i] = v;
        }

        // ---- load first tile: CCH x TY x 64 floats (always in bounds) ----
#pragma unroll 1
        for (int i = tid; i < CCH * TY * FV4; i += 256) {
            const int ch  = i / (TY * FV4);
            const int rem = i - ch * (TY * FV4);
            const int r   = rem / FV4;
            const int k   = rem - r * FV4;
            reinterpret_cast<float4*>(fst)[i] =
                *reinterpret_cast<const float4*>(
                    first + (((b * Cc + c0 + ch) * Hh + (y0 + r)) * Ww + x0 + k * 4));
        }
        __syncthreads();

        // ---- accumulate: per channel, per dy (j), 10 smem floats serve
        // 2 pixels x 9 dx = 18 FMAs ----
#pragma unroll 4
        for (int ch = 0; ch < CCH; ch++) {
            const float2 f =
                reinterpret_cast<const float2*>(fst)[(ch * TY + ty) * (TX / 2) + tx];
#pragma unroll
            for (int j = 0; j < 3; j++) {
                const float2* srow = reinterpret_cast<const float2*>(sec) +
                                     (ch * SROWS + ty + j) * (SW / 2) + tx;
                float s[10];
#pragma unroll
                for (int q = 0; q < 5; q++) {
                    const float2 v = srow[q];
                    s[2 * q]     = v.x;
                    s[2 * q + 1] = v.y;
                }
#pragma unroll
                for (int dxi = 0; dxi < 9; dxi++) {
                    acc[j][dxi][0] += f.x * s[dxi];
                    acc[j][dxi][1] += f.y * s[dxi + 1];
                }
            }
        }
    }

    // ---- write out 27 displacement planes x 2 pixels (float2 stores) ----
    const float inv = 1.0f / (float)Cc;
    const int x = x0 + tx * PXT;
    const int y = y0 + ty;
#pragma unroll
    for (int j = 0; j < 3; j++) {
#pragma unroll
        for (int dxi = 0; dxi < 9; dxi++) {
            const int d = (3 * g + j) * 9 + dxi;
            const float2 o = make_float2(acc[j][dxi][0] * inv,
                                         acc[j][dxi][1] * inv);
            *reinterpret_cast<float2*>(out + ((b * 81 + d) * Hh + y) * Ww + x) = o;
        }
    }
}

extern "C" void kernel_launch(void* const* d_in, const int* in_sizes, int n_in,
                              void* d_out, int out_size)
{
    const float* first  = (const float*)d_in[0];
    const float* second = (const float*)d_in[1];
    float* out          = (float*)d_out;

    cudaFuncSetAttribute(FunctionCorrelation_17282948399394_kernel,
                         cudaFuncAttributeMaxDynamicSharedMemorySize,
                         (int)SMEM_BYTES);

    dim3 block(GX, TY, 1);
    FunctionCorrelation_17282948399394_kernel<<<NBLOCKS, block, SMEM_BYTES>>>(
        first, second, out);
}

// round 6
// speedup vs baseline: 1.2924x; 1.2924x over previous
#include <cuda_runtime.h>

// Correlation cost volume (FlowNet-style), MAX_DISP=4 (81 displacements).
// first, second: [B=4, C=128, H=128, W=192] fp32.  out: [B, 81, H, W] fp32,
// out[b,(dy+4)*9+(dx+4),y,x] = (1/C) * sum_c first[b,c,y,x]*second[b,c,y+dy,x+dx]
//
// v2: cp.async double-buffered stages (loads overlap compute), precomputed
// per-thread load slots (no per-stage div/mod), fma.rn.f32x2 on even-dx taps.

namespace {
constexpr int Bb = 4, Cc = 128, Hh = 128, Ww = 192;
constexpr int PXT = 2;             // pixels per thread along x
constexpr int GX  = 32;            // thread columns
constexpr int TX  = GX * PXT;      // 64
constexpr int TY  = 8;
constexpr int CCH = 8;             // channels per stage
constexpr int NST = Cc / CCH;      // 16
constexpr int SROWS = TY + 2;      // 10 second rows per dy-group of 3
constexpr int SW  = TX + 8;        // 72 floats per second row
constexpr int XT  = Ww / TX;       // 3
constexpr int YT  = Hh / TY;       // 16
constexpr int SEC_F = CCH * SROWS * SW;   // 5760 floats
constexpr int FST_F = CCH * TY * TX;      // 4096 floats
constexpr int BUF_F = SEC_F + FST_F;      // 9856 floats per pipeline buffer
constexpr unsigned SMEM_BYTES = 2u * BUF_F * 4u;  // 78848 B -> 2 blocks/SM
constexpr int NBLOCKS = Bb * XT * YT * 3;  // 576
constexpr int SEC_V4 = SEC_F / 4;          // 1440 float4 per stage
constexpr int SEC_SLOTS = 6;               // ceil(1440/256)
constexpr int FST_SLOTS = 4;               // 1024/256
constexpr unsigned CH_STRIDE = (unsigned)CCH * Hh * Ww * 4u;   // 786432 B/stage
constexpr unsigned FST_SLOT_STRIDE = 2u * Hh * Ww * 4u;        // ch += 2 per slot
}  // namespace

__device__ __forceinline__ void cp16(unsigned sdst, const char* gsrc, unsigned sz) {
    asm volatile("cp.async.cg.shared.global [%0], [%1], 16, %2;\n"
                 :: "r"(sdst), "l"(gsrc), "r"(sz) : "memory");
}
__device__ __forceinline__ unsigned long long pack2(float x, float y) {
    unsigned long long r;
    asm("mov.b64 %0, {%1, %2};" : "=l"(r) : "f"(x), "f"(y));
    return r;
}
__device__ __forceinline__ void ffma2(unsigned long long& d,
                                      unsigned long long a, unsigned long long b) {
    asm("fma.rn.f32x2 %0, %1, %2, %0;" : "+l"(d) : "l"(a), "l"(b));
}
__device__ __forceinline__ void unpack2(unsigned long long v, float& lo, float& hi) {
    asm("mov.b64 {%0, %1}, %2;" : "=f"(lo), "=f"(hi) : "l"(v));
}

__global__ __launch_bounds__(256, 2)
void FunctionCorrelation_17282948399394_kernel(
    const float* __restrict__ first,
    const float* __restrict__ second,
    float* __restrict__ out)
{
    extern __shared__ float smem[];
    const unsigned smem_u32 = (unsigned)__cvta_generic_to_shared(smem);

    const int tx  = threadIdx.x;          // 0..31
    const int ty  = threadIdx.y;          // 0..7
    const int tid = ty * GX + tx;

    int t = blockIdx.x;
    const int g  = t % 3;  t /= 3;        // dy group: dy in {3g-4,3g-3,3g-2}
    const int xt = t % XT; t /= XT;
    const int yt = t % YT; t /= YT;
    const int b  = t;

    const int x0  = xt * TX;
    const int y0  = yt * TY;
    const int ys0 = y0 + 3 * g - 4;

    // ---- precompute load slots (stage-0 byte offsets; advance by CH_STRIDE) --
    unsigned secOff[SEC_SLOTS];
    unsigned secSz[SEC_SLOTS];
#pragma unroll
    for (int s = 0; s < SEC_SLOTS; s++) {
        const int i = s * 256 + tid;
        unsigned off = 0, sz = 0;
        if (i < SEC_V4) {
            const int ch  = i / (SROWS * (SW / 4));
            const int rem = i - ch * (SROWS * (SW / 4));
            const int r   = rem / (SW / 4);
            const int k   = rem - r * (SW / 4);
            const int gy  = ys0 + r;
            const int gx  = x0 - 4 + 4 * k;
            if ((unsigned)gy < (unsigned)Hh && (unsigned)gx < (unsigned)Ww) {
                off = (unsigned)((((b * Cc + ch) * Hh + gy) * Ww + gx) * 4);
                sz  = 16u;   // sz==0 -> cp.async zero-fills dst (halo padding)
            }
        }
        secOff[s] = off;
        secSz[s]  = sz;
    }
    // fst: i = s*256+tid -> ch = 2s + tid/128 (affine in slot), r,k from tid%128
    const int fch0 = tid >> 7;
    const int frr  = (tid & 127) >> 4;
    const int fkk  = tid & 15;
    const unsigned fstOff0 =
        (unsigned)((((b * Cc + fch0) * Hh + (y0 + frr)) * Ww + x0 + 4 * fkk) * 4);

    const char* secP = (const char*)second;
    const char* fstP = (const char*)first;

    auto issue_stage = [&](int buf, const char* sp, const char* fp) {
        const unsigned sbase = smem_u32 + (unsigned)buf * (BUF_F * 4u);
#pragma unroll
        for (int s = 0; s < SEC_SLOTS; s++) {
            if (s * 256 + tid < SEC_V4)
                cp16(sbase + (unsigned)(s * 256 + tid) * 16u, sp + secOff[s], secSz[s]);
        }
        const unsigned fbase = sbase + (unsigned)SEC_F * 4u;
#pragma unroll
        for (int s = 0; s < FST_SLOTS; s++) {
            cp16(fbase + (unsigned)(s * 256 + tid) * 16u,
                 fp + fstOff0 + (unsigned)s * FST_SLOT_STRIDE, 16u);
        }
        asm volatile("cp.async.commit_group;" ::: "memory");
    };

    // ---- accumulators: even dx as packed f32x2 over the pixel pair ----------
    unsigned long long acc2[3][5];   // dx = 0,2,4,6,8
    float acco[3][4][2];             // dx = 1,3,5,7
#pragma unroll
    for (int j = 0; j < 3; j++) {
#pragma unroll
        for (int q = 0; q < 5; q++) acc2[j][q] = 0ull;
#pragma unroll
        for (int o = 0; o < 4; o++) { acco[j][o][0] = 0.f; acco[j][o][1] = 0.f; }
    }

    // ---- pipelined main loop ------------------------------------------------
    issue_stage(0, secP, fstP);
    secP += CH_STRIDE; fstP += CH_STRIDE;

#pragma unroll 1
    for (int st = 0; st < NST; st++) {
        if (st + 1 < NST) {
            issue_stage((st + 1) & 1, secP, fstP);
            secP += CH_STRIDE; fstP += CH_STRIDE;
            asm volatile("cp.async.wait_group 1;" ::: "memory");
        } else {
            asm volatile("cp.async.wait_group 0;" ::: "memory");
        }
        __syncthreads();

        const float2* secb = (const float2*)(smem + (st & 1) * BUF_F);
        const float2* fstb = (const float2*)(smem + (st & 1) * BUF_F + SEC_F);

#pragma unroll
        for (int ch = 0; ch < CCH; ch++) {
            const float2 f = fstb[(ch * TY + ty) * (TX / 2) + tx];
            const unsigned long long fp = pack2(f.x, f.y);
#pragma unroll
            for (int j = 0; j < 3; j++) {
                const float2* sr = secb + (ch * SROWS + ty + j) * (SW / 2) + tx;
                const float2 s0 = sr[0], s1 = sr[1], s2 = sr[2], s3 = sr[3], s4 = sr[4];
                // even dx: acc.lo += f.x*s[2q], acc.hi += f.y*s[2q+1]
                ffma2(acc2[j][0], fp, pack2(s0.x, s0.y));
                ffma2(acc2[j][1], fp, pack2(s1.x, s1.y));
                ffma2(acc2[j][2], fp, pack2(s2.x, s2.y));
                ffma2(acc2[j][3], fp, pack2(s3.x, s3.y));
                ffma2(acc2[j][4], fp, pack2(s4.x, s4.y));
                // odd dx d: acc[d][0] += f.x*s[d]; acc[d][1] += f.y*s[d+1]
                acco[j][0][0] += f.x * s0.y;  acco[j][0][1] += f.y * s1.x;
                acco[j][1][0] += f.x * s1.y;  acco[j][1][1] += f.y * s2.x;
                acco[j][2][0] += f.x * s2.y;  acco[j][2][1] += f.y * s3.x;
                acco[j][3][0] += f.x * s3.y;  acco[j][3][1] += f.y * s4.x;
            }
        }
        __syncthreads();   // all reads of this buffer done before it is refilled
    }

    // ---- epilogue -----------------------------------------------------------
    const float inv = 1.0f / (float)Cc;
    const int x = x0 + tx * PXT;
    const int y = y0 + ty;
#pragma unroll
    for (int j = 0; j < 3; j++) {
        const int dyi = 3 * g + j;
#pragma unroll
        for (int q = 0; q < 5; q++) {              // dx index 2q
            float lo, hi;
            unpack2(acc2[j][q], lo, hi);
            const int d = dyi * 9 + 2 * q;
            *reinterpret_cast<float2*>(out + ((b * 81 + d) * Hh + y) * Ww + x) =
                make_float2(lo * inv, hi * inv);
        }
#pragma unroll
        for (int o = 0; o < 4; o++) {              // dx index 2o+1
            const int d = dyi * 9 + 2 * o + 1;
            *reinterpret_cast<float2*>(out + ((b * 81 + d) * Hh + y) * Ww + x) =
                make_float2(acco[j][o][0] * inv, acco[j][o][1] * inv);
        }
    }
}

extern "C" void kernel_launch(void* const* d_in, const int* in_sizes, int n_in,
                              void* d_out, int out_size)
{
    const float* first  = (const float*)d_in[0];
    const float* second = (const float*)d_in[1];
    float* out          = (float*)d_out;

    cudaFuncSetAttribute(FunctionCorrelation_17282948399394_kernel,
                         cudaFuncAttributeMaxDynamicSharedMemorySize,
                         (int)SMEM_BYTES);

    dim3 block(GX, TY, 1);
    FunctionCorrelation_17282948399394_kernel<<<NBLOCKS, block, SMEM_BYTES>>>(
        first, second, out);
}

// round 7
// speedup vs baseline: 2.7836x; 2.1539x over previous
#include <cuda_runtime.h>

// Correlation cost volume (FlowNet-style), MAX_DISP=4 (81 displacements).
// first, second: [B=4, C=128, H=128, W=192] fp32.  out: [B, 81, H, W] fp32,
// out[b,(dy+4)*9+(dx+4),y,x] = (1/C) * sum_c first[b,c,y,x]*second[b,c,y+dy,x+dx]
//
// v3: 4 pixels/thread (1.48 smem B per FMA, was 2.37), 128-thread blocks,
// cp.async double-buffered stages, f32x2 FMA on even-dx taps.

namespace {
constexpr int Bb = 4, Cc = 128, Hh = 128, Ww = 192;
constexpr int PXT = 4;             // pixels per thread along x
constexpr int GX  = 16;            // thread columns
constexpr int TX  = GX * PXT;      // 64
constexpr int TY  = 8;
constexpr int NT  = GX * TY;       // 128 threads/block
constexpr int CCH = 8;             // channels per stage
constexpr int NST = Cc / CCH;      // 16
constexpr int SROWS = TY + 2;      // 10 second rows per dy-group of 3
constexpr int SW  = TX + 8;        // 72 floats per second row
constexpr int XT  = Ww / TX;       // 3
constexpr int YT  = Hh / TY;       // 16
constexpr int SEC_F = CCH * SROWS * SW;   // 5760 floats
constexpr int FST_F = CCH * TY * TX;      // 4096 floats
constexpr int BUF_F = SEC_F + FST_F;      // 9856 floats per pipeline buffer
constexpr unsigned SMEM_BYTES = 2u * BUF_F * 4u;  // 78848 B -> 2 blocks/SM
constexpr int NBLOCKS = Bb * XT * YT * 3;  // 576 (1.95 waves @ 296 concurrent)
constexpr int SEC_V4 = SEC_F / 4;          // 1440 float4 per stage
constexpr int SEC_SLOTS = 12;              // ceil(1440/128); slot 11 partial
constexpr int SROW_V4 = SW / 4;            // 18
constexpr unsigned CH_STRIDE = (unsigned)CCH * Hh * Ww * 4u;   // bytes per stage
constexpr unsigned PLANE = (unsigned)Hh * Ww * 4u;             // one channel plane
}  // namespace

__device__ __forceinline__ void cp16(unsigned sdst, const char* gsrc, unsigned sz) {
    asm volatile("cp.async.cg.shared.global [%0], [%1], 16, %2;\n"
                 :: "r"(sdst), "l"(gsrc), "r"(sz) : "memory");
}
__device__ __forceinline__ unsigned long long pack2(float x, float y) {
    unsigned long long r;
    asm("mov.b64 %0, {%1, %2};" : "=l"(r) : "f"(x), "f"(y));
    return r;
}
__device__ __forceinline__ void ffma2(unsigned long long& d,
                                      unsigned long long a, unsigned long long b) {
    asm("fma.rn.f32x2 %0, %1, %2, %0;" : "+l"(d) : "l"(a), "l"(b));
}
__device__ __forceinline__ void unpack2(unsigned long long v, float& lo, float& hi) {
    asm("mov.b64 {%0, %1}, %2;" : "=f"(lo), "=f"(hi) : "l"(v));
}

__global__ __launch_bounds__(NT, 2)
void FunctionCorrelation_17282948399394_kernel(
    const float* __restrict__ first,
    const float* __restrict__ second,
    float* __restrict__ out)
{
    extern __shared__ float smem[];
    const unsigned smem_u32 = (unsigned)__cvta_generic_to_shared(smem);

    const int tx  = threadIdx.x;          // 0..15
    const int ty  = threadIdx.y;          // 0..7
    const int tid = ty * GX + tx;         // 0..127

    int t = blockIdx.x;
    const int g  = t % 3;  t /= 3;        // dy group: dy in {3g-4,3g-3,3g-2}
    const int xt = t % XT; t /= XT;
    const int yt = t % YT; t /= YT;
    const int b  = t;

    const int x0  = xt * TX;
    const int y0  = yt * TY;
    const int ys0 = y0 + 3 * g - 4;

    // ---- precompute second-tile load slots (stage-0 byte offsets) -----------
    unsigned secOff[SEC_SLOTS];
    unsigned vmask = 0;                   // bit s set -> in-bounds (sz=16)
#pragma unroll
    for (int s = 0; s < SEC_SLOTS; s++) {
        const int i = s * NT + tid;
        unsigned off = 0;
        if (i < SEC_V4) {
            const int ch  = i / (SROWS * SROW_V4);
            const int rem = i - ch * (SROWS * SROW_V4);
            const int r   = rem / SROW_V4;
            const int k   = rem - r * SROW_V4;
            const int gy  = ys0 + r;
            const int gx  = x0 - 4 + 4 * k;
            if ((unsigned)gy < (unsigned)Hh && (unsigned)gx < (unsigned)Ww) {
                off = (unsigned)((((b * Cc + ch) * Hh + gy) * Ww + gx) * 4);
                vmask |= 1u << s;
            }
        }
        secOff[s] = off;
    }
    // first tile: 128 threads == one channel plane per slot (ch = slot)
    const int frr = tid >> 4;             // row 0..7
    const int fkk = tid & 15;             // float4 col 0..15
    const unsigned fstOff0 =
        (unsigned)(((b * Cc * Hh + (y0 + frr)) * Ww + x0 + 4 * fkk) * 4);

    const char* secP = (const char*)second;
    const char* fstP = (const char*)first;

    auto issue_stage = [&](int buf, const char* sp, const char* fp) {
        const unsigned sbase = smem_u32 + (unsigned)buf * (BUF_F * 4u);
#pragma unroll
        for (int s = 0; s < SEC_SLOTS; s++) {
            if (s < SEC_SLOTS - 1 || tid < (SEC_V4 - (SEC_SLOTS - 1) * NT))
                cp16(sbase + (unsigned)(s * NT + tid) * 16u, sp + secOff[s],
                     ((vmask >> s) & 1u) ? 16u : 0u);
        }
        const unsigned fbase = sbase + (unsigned)SEC_F * 4u;
#pragma unroll
        for (int s = 0; s < CCH; s++) {
            cp16(fbase + (unsigned)(s * NT + tid) * 16u,
                 fp + fstOff0 + (unsigned)s * PLANE, 16u);
        }
        asm volatile("cp.async.commit_group;" ::: "memory");
    };

    // ---- accumulators: even dx packed f32x2 over pixel pairs ---------------
    unsigned long long acc2[3][5][2];     // [j][dx/2][pixel-pair]
    float acco[3][4][4];                  // [j][(dx-1)/2][pixel]
#pragma unroll
    for (int j = 0; j < 3; j++) {
#pragma unroll
        for (int q = 0; q < 5; q++) { acc2[j][q][0] = 0ull; acc2[j][q][1] = 0ull; }
#pragma unroll
        for (int o = 0; o < 4; o++)
#pragma unroll
            for (int p = 0; p < 4; p++) acco[j][o][p] = 0.f;
    }

    // ---- pipelined main loop ------------------------------------------------
    issue_stage(0, secP, fstP);
    secP += CH_STRIDE; fstP += CH_STRIDE;

#pragma unroll 1
    for (int st = 0; st < NST; st++) {
        if (st + 1 < NST) {
            issue_stage((st + 1) & 1, secP, fstP);
            secP += CH_STRIDE; fstP += CH_STRIDE;
            asm volatile("cp.async.wait_group 1;" ::: "memory");
        } else {
            asm volatile("cp.async.wait_group 0;" ::: "memory");
        }
        __syncthreads();

        const float4* secb = (const float4*)(smem + (st & 1) * BUF_F);
        const float4* fstb = (const float4*)(smem + (st & 1) * BUF_F + SEC_F);

#pragma unroll
        for (int ch = 0; ch < CCH; ch++) {
            const float4 f = fstb[(ch * TY + ty) * (TX / 4) + tx];
            const unsigned long long fp0 = pack2(f.x, f.y);
            const unsigned long long fp1 = pack2(f.z, f.w);
#pragma unroll
            for (int j = 0; j < 3; j++) {
                const float4* sr = secb + (ch * SROWS + ty + j) * SROW_V4 + tx;
                const float4 a = sr[0], c = sr[1], e = sr[2];
                // s[0..11] = a.x a.y a.z a.w c.x c.y c.z c.w e.x e.y e.z e.w
                const unsigned long long P0 = pack2(a.x, a.y);
                const unsigned long long P1 = pack2(a.z, a.w);
                const unsigned long long P2 = pack2(c.x, c.y);
                const unsigned long long P3 = pack2(c.z, c.w);
                const unsigned long long P4 = pack2(e.x, e.y);
                const unsigned long long P5 = pack2(e.z, e.w);
                // even dx = 2q: pixel pair 0 uses s[2q:2q+1], pair 1 uses s[2q+2:2q+3]
                ffma2(acc2[j][0][0], fp0, P0);  ffma2(acc2[j][0][1], fp1, P1);
                ffma2(acc2[j][1][0], fp0, P1);  ffma2(acc2[j][1][1], fp1, P2);
                ffma2(acc2[j][2][0], fp0, P2);  ffma2(acc2[j][2][1], fp1, P3);
                ffma2(acc2[j][3][0], fp0, P3);  ffma2(acc2[j][3][1], fp1, P4);
                ffma2(acc2[j][4][0], fp0, P4);  ffma2(acc2[j][4][1], fp1, P5);
                // odd dx = 2o+1: acco[j][o][p] += f[p] * s[2o+1+p]
                acco[j][0][0] += f.x * a.y;  acco[j][0][1] += f.y * a.z;
                acco[j][0][2] += f.z * a.w;  acco[j][0][3] += f.w * c.x;
                acco[j][1][0] += f.x * a.w;  acco[j][1][1] += f.y * c.x;
                acco[j][1][2] += f.z * c.y;  acco[j][1][3] += f.w * c.z;
                acco[j][2][0] += f.x * c.y;  acco[j][2][1] += f.y * c.z;
                acco[j][2][2] += f.z * c.w;  acco[j][2][3] += f.w * e.x;
                acco[j][3][0] += f.x * c.w;  acco[j][3][1] += f.y * e.x;
                acco[j][3][2] += f.z * e.y;  acco[j][3][3] += f.w * e.z;
            }
        }
        __syncthreads();   // all reads of this buffer done before it is refilled
    }

    // ---- epilogue: 27 planes x 4 pixels, float4 stores ----------------------
    const float inv = 1.0f / (float)Cc;
    const int x = x0 + tx * PXT;
    const int y = y0 + ty;
#pragma unroll
    for (int j = 0; j < 3; j++) {
        const int dyi = 3 * g + j;
#pragma unroll
        for (int q = 0; q < 5; q++) {              // dx index 2q
            float v0, v1, v2, v3;
            unpack2(acc2[j][q][0], v0, v1);
            unpack2(acc2[j][q][1], v2, v3);
            const int d = dyi * 9 + 2 * q;
            *reinterpret_cast<float4*>(out + ((b * 81 + d) * Hh + y) * Ww + x) =
                make_float4(v0 * inv, v1 * inv, v2 * inv, v3 * inv);
        }
#pragma unroll
        for (int o = 0; o < 4; o++) {              // dx index 2o+1
            const int d = dyi * 9 + 2 * o + 1;
            *reinterpret_cast<float4*>(out + ((b * 81 + d) * Hh + y) * Ww + x) =
                make_float4(acco[j][o][0] * inv, acco[j][o][1] * inv,
                            acco[j][o][2] * inv, acco[j][o][3] * inv);
        }
    }
}

extern "C" void kernel_launch(void* const* d_in, const int* in_sizes, int n_in,
                              void* d_out, int out_size)
{
    const float* first  = (const float*)d_in[0];
    const float* second = (const float*)d_in[1];
    float* out          = (float*)d_out;

    cudaFuncSetAttribute(FunctionCorrelation_17282948399394_kernel,
                         cudaFuncAttributeMaxDynamicSharedMemorySize,
                         (int)SMEM_BYTES);

    dim3 block(GX, TY, 1);
    FunctionCorrelation_17282948399394_kernel<<<NBLOCKS, block, SMEM_BYTES>>>(
        first, second, out);
}